// round 10
// baseline (speedup 1.0000x reference)
#include <cuda_runtime.h>

#define B_ 16
#define ORDER_ 2
#define N_ 512
#define D_ 128
#define H_ 8
#define DH_ 16
#define NBIC 64   // B*ORDER*2 (b,i,c) combos

// ---------------- scratch (device globals; no allocations) ----------------
__device__ __align__(16) float g_xp  [NBIC * N_ * D_];       // projected features (+pb)
__device__ __align__(16) float g_src4[NBIC * N_ * H_ * 4];   // {ssrc, exp(ssrc), exp(.2 ssrc), 0}
__device__ __align__(16) float g_dst4[NBIC * N_ * H_ * 4];   // {sdst, exp(sdst), exp(.2 sdst), 0}
__device__ __align__(16) unsigned int g_mask[NBIC * N_ * (N_ / 32)]; // 1 bit per edge (2 MB)
__device__ __align__(16) float g_att [NBIC * N_ * D_];       // per-conv GAT output (+xp +bias)

// ---------------- packed f32x2 helpers ----------------
__device__ __forceinline__ unsigned long long pk2(float a, float b) {
    unsigned long long r;
    asm("mov.b64 %0, {%1, %2};" : "=l"(r) : "r"(__float_as_uint(a)), "r"(__float_as_uint(b)));
    return r;
}
__device__ __forceinline__ void upk2(unsigned long long v, float& a, float& b) {
    unsigned int lo, hi;
    asm("mov.b64 {%0, %1}, %2;" : "=r"(lo), "=r"(hi) : "l"(v));
    a = __uint_as_float(lo); b = __uint_as_float(hi);
}
__device__ __forceinline__ void fma2(unsigned long long& d, unsigned long long a, unsigned long long b) {
    asm("fma.rn.f32x2 %0, %1, %2, %0;" : "+l"(d) : "l"(a), "l"(b));
}
__device__ __forceinline__ void cpa16(unsigned int s, const void* g) {
    asm volatile("cp.async.cg.shared.global [%0], [%1], 16;" :: "r"(s), "l"(g) : "memory");
}
__device__ __forceinline__ void cpa_commit() {
    asm volatile("cp.async.commit_group;" ::: "memory");
}
__device__ __forceinline__ void cpa_wait0() {
    asm volatile("cp.async.wait_group 0;" ::: "memory");
}

// ============================================================================
// Kernel 0: bit-packed edge masks via ballot.
// warp = (bi, s, w); lane = dst w*32+lane.  m0: c=0 (A==2|4), m1: c=1 (A==3|4)
// g_mask[((bi*2+c)*512 + s)*16 + w], bit j = edge(s, w*32+j)
// ============================================================================
__global__ __launch_bounds__(256) void mask_kernel(const int* __restrict__ A) {
    int gid  = blockIdx.x * 256 + threadIdx.x;
    int lane = gid & 31;
    int wlin = gid >> 5;            // 0 .. 32*512*16-1
    int bi   = wlin >> 13;          // 8192 warps per bi
    int rr   = wlin & 8191;
    int s    = rr >> 4, w = rr & 15;
    int a = A[((size_t)(bi * N_ + s)) * N_ + w * 32 + lane];
    unsigned int m0 = __ballot_sync(0xffffffffu, a == 4 || a == 2);
    unsigned int m1 = __ballot_sync(0xffffffffu, a == 4 || a == 3);
    if (lane == 0) g_mask[((size_t)(bi * 2 + 0) * N_ + s) * 16 + w] = m0;
    if (lane == 1) g_mask[((size_t)(bi * 2 + 1) * N_ + s) * 16 + w] = m1;
}

// ============================================================================
// Kernel 1: projection xp = x @ W^T + pb  (per (b,i,c)),
//           fused epilogue computes ssrc/sdst head dots AND their exp forms.
// grid: (8 n-tiles, 64 bic), block 256.
// ============================================================================
__global__ __launch_bounds__(256) void proj_kernel(
    const float* __restrict__ x, const float* __restrict__ W, const float* __restrict__ pb,
    const float* __restrict__ asrc, const float* __restrict__ adst)
{
    const int bic  = blockIdx.y;
    const int nt   = blockIdx.x;
    const int c    = bic & 1;
    const int bi   = bic >> 1;
    const int iord = bi & 1;
    const int tid  = threadIdx.x;
    const int lane = tid & 31, warp = tid >> 5;

    __shared__ __align__(16) float xs[64][36];    // [n][k] (pad 4)
    __shared__ __align__(16) float wt[32][128];   // [k][d], XOR-swizzled float4 columns

    const float* xb = x + ((size_t)bi * N_ + nt * 64) * D_;
    const float* Wb = W + (size_t)(iord * 2 + c) * D_ * D_;

    unsigned long long acc[8][2];
#pragma unroll
    for (int r = 0; r < 8; r++) { acc[r][0] = 0ull; acc[r][1] = 0ull; }

    for (int kc = 0; kc < 4; kc++) {
        __syncthreads();
#pragma unroll
        for (int t2 = 0; t2 < 2; t2++) {
            int fid = tid + t2 * 256;
            int s = fid >> 3, kq = fid & 7;
            float4 v = *(const float4*)(xb + (size_t)s * D_ + kc * 32 + kq * 4);
            *(float4*)&xs[s][kq * 4] = v;
        }
#pragma unroll
        for (int t4 = 0; t4 < 4; t4++) {
            int fid = tid + t4 * 256;
            int d = fid >> 3, kq = fid & 7;
            float4 v = *(const float4*)(Wb + (size_t)d * D_ + kc * 32 + kq * 4);
            int d4 = d >> 2, dr = d & 3;
            wt[kq * 4 + 0][((d4 ^ (kq * 4 + 0)) << 2) + dr] = v.x;
            wt[kq * 4 + 1][((d4 ^ (kq * 4 + 1)) << 2) + dr] = v.y;
            wt[kq * 4 + 2][((d4 ^ (kq * 4 + 2)) << 2) + dr] = v.z;
            wt[kq * 4 + 3][((d4 ^ (kq * 4 + 3)) << 2) + dr] = v.w;
        }
        __syncthreads();
#pragma unroll 4
        for (int k = 0; k < 32; k++) {
            float4 wv = *(const float4*)&wt[k][(lane ^ k) << 2];
            unsigned long long w01 = pk2(wv.x, wv.y);
            unsigned long long w23 = pk2(wv.z, wv.w);
#pragma unroll
            for (int r = 0; r < 8; r++) {
                float a = xs[warp * 8 + r][k];
                unsigned long long a2 = pk2(a, a);
                fma2(acc[r][0], a2, w01);
                fma2(acc[r][1], a2, w23);
            }
        }
    }

    const float4 pbv = *(const float4*)(pb + (iord * 2 + c) * D_ + lane * 4);
    const int h  = lane >> 2;
    const int fb = (lane & 3) * 4;
    const float4 av = *(const float4*)(asrc + ((iord * 2 + c) * H_ + h) * DH_ + fb);
    const float4 dv = *(const float4*)(adst + ((iord * 2 + c) * H_ + h) * DH_ + fb);
#pragma unroll
    for (int r = 0; r < 8; r++) {
        int n = nt * 64 + warp * 8 + r;
        float x0, x1, x2, x3;
        upk2(acc[r][0], x0, x1);
        upk2(acc[r][1], x2, x3);
        x0 += pbv.x; x1 += pbv.y; x2 += pbv.z; x3 += pbv.w;
        *(float4*)(g_xp + ((size_t)bic * N_ + n) * D_ + lane * 4) = make_float4(x0, x1, x2, x3);
        float ps = x0 * av.x + x1 * av.y + x2 * av.z + x3 * av.w;
        float pd = x0 * dv.x + x1 * dv.y + x2 * dv.z + x3 * dv.w;
        ps += __shfl_xor_sync(0xffffffffu, ps, 1);
        ps += __shfl_xor_sync(0xffffffffu, ps, 2);
        pd += __shfl_xor_sync(0xffffffffu, pd, 1);
        pd += __shfl_xor_sync(0xffffffffu, pd, 2);
        if ((lane & 3) == 0) {
            size_t o = ((size_t)bic * N_ + n) * H_ + h;
            *(float4*)(g_src4 + o * 4) = make_float4(ps, __expf(ps), __expf(0.2f * ps), 0.0f);
            *(float4*)(g_dst4 + o * 4) = make_float4(pd, __expf(pd), __expf(0.2f * pd), 0.0f);
        }
    }
}

// ============================================================================
// Kernel 2: attention, cp.async double-buffered, MUFU-free, 4-dst blocking,
//           bit-packed edge masks, deduped score computation.
// grid: (4 dst-tiles of 128, 64 bic), block 256.
// Per-buffer float layout: [0,5120) xh(32x160, head-stride 20)
//                          [5120,6144) ss(32x32)  [6144,6272) mask (32 s x 4 u32)
// ============================================================================
#define TS 32
#define BUF_FLOATS 6272

__global__ __launch_bounds__(256, 2) void att_kernel(const float* __restrict__ bias)
{
    extern __shared__ __align__(16) float smem[];
    const int bic  = blockIdx.y;
    const int tile = blockIdx.x;
    const int c    = bic & 1;
    const int bi   = bic >> 1;
    const int iord = bi & 1;
    const int tid  = threadIdx.x;
    const int h    = tid & 7;
    const int dl   = tid >> 3;             // 0..31
    const int dst0 = tile * 128 + dl * 4;  // 4 consecutive dsts
    const int wsel = dl >> 3;              // mask word within the 4 covering this tile
    const int shft = (dl & 7) * 4;         // bit offset of this thread's 4 dsts

    unsigned int sbase;
    asm("{.reg .u64 t; cvta.to.shared.u64 t, %1; cvt.u32.u64 %0, t;}"
        : "=r"(sbase) : "l"(smem));

    const float* xp    = g_xp   + (size_t)bic * N_ * D_;
    const float* src4p = g_src4 + (size_t)bic * N_ * H_ * 4;
    const unsigned int* mgp = g_mask + (size_t)bic * N_ * 16 + tile * 4;

    const int xs_s = tid >> 5, xs_dq = tid & 31;  // +k*8 rows
    const int ss_s = tid >> 3, ss_h = tid & 7;

    float sd[4], q1[4], q2[4], Z[4];
#pragma unroll
    for (int d = 0; d < 4; d++) {
        float4 v = *(const float4*)(g_dst4 + (((size_t)bic * N_ + dst0 + d) * H_ + h) * 4);
        sd[d] = v.x; q1[d] = v.y; q2[d] = v.z; Z[d] = 0.0f;
    }

    unsigned long long acc[4][8];
#pragma unroll
    for (int d = 0; d < 4; d++)
#pragma unroll
        for (int j = 0; j < 8; j++) acc[d][j] = 0ull;

    auto issue = [&](int t, int buf) {
        const int s0 = t * TS;
        const unsigned int b = sbase + buf * (BUF_FLOATS * 4);
#pragma unroll
        for (int k = 0; k < 4; k++) {
            int s = xs_s + k * 8;
            cpa16(b + (unsigned)(s * 640 + (xs_dq >> 2) * 80 + (xs_dq & 3) * 16),
                  xp + (size_t)(s0 + s) * D_ + xs_dq * 4);
        }
        cpa16(b + 20480u + (unsigned)(ss_s * 128 + ss_h * 16),
              src4p + ((size_t)(s0 + ss_s) * H_ + ss_h) * 4);
        if (tid < 32)
            cpa16(b + 24576u + (unsigned)(tid * 16), mgp + (size_t)(s0 + tid) * 16);
        cpa_commit();
    };

    issue(0, 0);

#pragma unroll 1
    for (int t = 0; t < N_ / TS; t++) {
        const int p = t & 1;
        cpa_wait0();
        __syncthreads();
        if (t < N_ / TS - 1) issue(t + 1, 1 - p);

        const float* xhp = smem + p * BUF_FLOATS;
        const float* ssp = xhp + 5120;
        const unsigned int* mkp = (const unsigned int*)(xhp + 6144);
#pragma unroll 4
        for (int s = 0; s < TS; s++) {
            float4 ssv = *(const float4*)(ssp + s * 32 + h * 4);     // {ss, p1, p2, -}
            unsigned int bits = mkp[s * 4 + wsel] >> shft;           // 4 edge bits
            const ulonglong2* xr = (const ulonglong2*)(xhp + s * 160 + h * 20);
            ulonglong2 xA = xr[0], xB = xr[1], xC = xr[2], xD = xr[3];

            float eb4[4];
#pragma unroll
            for (int d = 0; d < 4; d++) {
                float t0 = ssv.x + sd[d];
                bool ge  = (t0 >= 0.0f);
                float pa = ge ? ssv.y : ssv.z;       // exp(ss) or exp(.2 ss)
                float qa = ge ? q1[d] : q2[d];       // exp(sd) or exp(.2 sd)
                float e  = pa * qa;                  // exp(lrelu(ss+sd))
                float eb = (bits & (1u << d)) ? e : 1.0f;  // edge? e : 1
                Z[d] += eb;
                eb4[d] = eb;
            }
#pragma unroll
            for (int d = 0; d < 4; d++) {
                unsigned long long e2 = pk2(eb4[d], eb4[d]);
                fma2(acc[d][0], e2, xA.x);
                fma2(acc[d][1], e2, xA.y);
                fma2(acc[d][2], e2, xB.x);
                fma2(acc[d][3], e2, xB.y);
                fma2(acc[d][4], e2, xC.x);
                fma2(acc[d][5], e2, xC.y);
                fma2(acc[d][6], e2, xD.x);
                fma2(acc[d][7], e2, xD.y);
            }
        }
    }

    // epilogue: /Z, + xp (add_self_loops), + bias
    float4 bq[4];
#pragma unroll
    for (int jj = 0; jj < 4; jj++)
        bq[jj] = *(const float4*)(bias + (iord * 2 + c) * D_ + h * DH_ + jj * 4);
#pragma unroll
    for (int d = 0; d < 4; d++) {
        const float invZ = 1.0f / Z[d];
        const float* xpd  = xp + (size_t)(dst0 + d) * D_ + h * DH_;
        float*       outp = g_att + (size_t)bic * N_ * D_ + (size_t)(dst0 + d) * D_ + h * DH_;
#pragma unroll
        for (int jj = 0; jj < 4; jj++) {
            float f0, f1, f2, f3;
            upk2(acc[d][2 * jj],     f0, f1);
            upk2(acc[d][2 * jj + 1], f2, f3);
            float4 xq = *(const float4*)(xpd + jj * 4);
            float4 o;
            o.x = f0 * invZ + xq.x + bq[jj].x;
            o.y = f1 * invZ + xq.y + bq[jj].y;
            o.z = f2 * invZ + xq.z + bq[jj].z;
            o.w = f3 * invZ + xq.w + bq[jj].w;
            *(float4*)(outp + jj * 4) = o;
        }
    }
}

// ============================================================================
// Kernel 3: combine.  h[b,i] = att[b,i,0] + att[b,i,1];
//           out[b,i] = h[b,i] + 0.5*(h[b,0] + h[b,1])
// ============================================================================
__global__ void combine_kernel(float4* __restrict__ out) {
    int gid = blockIdx.x * blockDim.x + threadIdx.x;   // 0 .. 16*16384-1
    int b = gid >> 14;
    int r = gid & 16383;
    const float4* a = (const float4*)g_att;
    float4 a00 = a[(size_t)(b * 4 + 0) * 16384 + r];
    float4 a01 = a[(size_t)(b * 4 + 1) * 16384 + r];
    float4 a10 = a[(size_t)(b * 4 + 2) * 16384 + r];
    float4 a11 = a[(size_t)(b * 4 + 3) * 16384 + r];
    float4 h0, h1, o0, o1;
    h0.x = a00.x + a01.x; h0.y = a00.y + a01.y; h0.z = a00.z + a01.z; h0.w = a00.w + a01.w;
    h1.x = a10.x + a11.x; h1.y = a10.y + a11.y; h1.z = a10.z + a11.z; h1.w = a10.w + a11.w;
    float mx = 0.5f * (h0.x + h1.x), my = 0.5f * (h0.y + h1.y);
    float mz = 0.5f * (h0.z + h1.z), mw = 0.5f * (h0.w + h1.w);
    o0.x = h0.x + mx; o0.y = h0.y + my; o0.z = h0.z + mz; o0.w = h0.w + mw;
    o1.x = h1.x + mx; o1.y = h1.y + my; o1.z = h1.z + mz; o1.w = h1.w + mw;
    out[(size_t)(b * 2 + 0) * 16384 + r] = o0;
    out[(size_t)(b * 2 + 1) * 16384 + r] = o1;
}

// ============================================================================
extern "C" void kernel_launch(void* const* d_in, const int* in_sizes, int n_in,
                              void* d_out, int out_size) {
    const float* x    = (const float*)d_in[0];
    const int*   A    = (const int*)  d_in[1];
    const float* W    = (const float*)d_in[2];
    const float* pb   = (const float*)d_in[3];
    const float* asrc = (const float*)d_in[4];
    const float* adst = (const float*)d_in[5];
    const float* bias = (const float*)d_in[6];

    cudaFuncSetAttribute(att_kernel, cudaFuncAttributeMaxDynamicSharedMemorySize,
                         2 * BUF_FLOATS * 4);

    mask_kernel<<<32768, 256>>>(A);
    proj_kernel<<<dim3(8, 64), 256>>>(x, W, pb, asrc, adst);
    att_kernel<<<dim3(4, 64), 256, 2 * BUF_FLOATS * 4>>>(bias);
    combine_kernel<<<1024, 256>>>((float4*)d_out);
}

// round 11
// speedup vs baseline: 1.0135x; 1.0135x over previous
#include <cuda_runtime.h>

#define B_ 16
#define ORDER_ 2
#define N_ 512
#define D_ 128
#define H_ 8
#define DH_ 16
#define NBIC 64   // B*ORDER*2 (b,i,c) combos

// ---------------- scratch (device globals; no allocations) ----------------
__device__ __align__(16) float g_xp  [NBIC * N_ * D_];       // projected features (+pb)
__device__ __align__(16) float g_src4[NBIC * N_ * H_ * 4];   // {ssrc, exp(ssrc), exp(.2 ssrc), 0}
__device__ __align__(16) float g_dst4[NBIC * N_ * H_ * 4];   // {sdst, exp(sdst), exp(.2 sdst), 0}
__device__ __align__(16) unsigned int g_mask[NBIC * N_ * (N_ / 32)]; // 1 bit per edge (2 MB)
__device__ __align__(16) float g_att [NBIC * N_ * D_];       // per-conv GAT output (+xp +bias)

// ---------------- packed f32x2 helpers ----------------
__device__ __forceinline__ unsigned long long pk2(float a, float b) {
    unsigned long long r;
    asm("mov.b64 %0, {%1, %2};" : "=l"(r) : "r"(__float_as_uint(a)), "r"(__float_as_uint(b)));
    return r;
}
__device__ __forceinline__ void upk2(unsigned long long v, float& a, float& b) {
    unsigned int lo, hi;
    asm("mov.b64 {%0, %1}, %2;" : "=r"(lo), "=r"(hi) : "l"(v));
    a = __uint_as_float(lo); b = __uint_as_float(hi);
}
__device__ __forceinline__ void fma2(unsigned long long& d, unsigned long long a, unsigned long long b) {
    asm("fma.rn.f32x2 %0, %1, %2, %0;" : "+l"(d) : "l"(a), "l"(b));
}
__device__ __forceinline__ void cpa16(unsigned int s, const void* g) {
    asm volatile("cp.async.cg.shared.global [%0], [%1], 16;" :: "r"(s), "l"(g) : "memory");
}
__device__ __forceinline__ void cpa_commit() {
    asm volatile("cp.async.commit_group;" ::: "memory");
}
__device__ __forceinline__ void cpa_wait0() {
    asm volatile("cp.async.wait_group 0;" ::: "memory");
}

// ============================================================================
// Kernel 0: bit-packed edge masks via ballot.
// warp = (bi, s, w); lane = dst w*32+lane.  m0: c=0 (A==2|4), m1: c=1 (A==3|4)
// g_mask[((bi*2+c)*512 + s)*16 + w], bit j = edge(s, w*32+j)
// ============================================================================
__global__ __launch_bounds__(256) void mask_kernel(const int* __restrict__ A) {
    int gid  = blockIdx.x * 256 + threadIdx.x;
    int lane = gid & 31;
    int wlin = gid >> 5;            // 0 .. 32*512*16-1
    int bi   = wlin >> 13;          // 8192 warps per bi
    int rr   = wlin & 8191;
    int s    = rr >> 4, w = rr & 15;
    int a = A[((size_t)(bi * N_ + s)) * N_ + w * 32 + lane];
    unsigned int m0 = __ballot_sync(0xffffffffu, a == 4 || a == 2);
    unsigned int m1 = __ballot_sync(0xffffffffu, a == 4 || a == 3);
    if (lane == 0) g_mask[((size_t)(bi * 2 + 0) * N_ + s) * 16 + w] = m0;
    if (lane == 1) g_mask[((size_t)(bi * 2 + 1) * N_ + s) * 16 + w] = m1;
}

// ============================================================================
// Kernel 1: projection xp = x @ W^T + pb  (per (b,i,c)),
//           fused epilogue computes ssrc/sdst head dots AND their exp forms.
// grid: (8 n-tiles, 64 bic), block 256.
// ============================================================================
__global__ __launch_bounds__(256) void proj_kernel(
    const float* __restrict__ x, const float* __restrict__ W, const float* __restrict__ pb,
    const float* __restrict__ asrc, const float* __restrict__ adst)
{
    const int bic  = blockIdx.y;
    const int nt   = blockIdx.x;
    const int c    = bic & 1;
    const int bi   = bic >> 1;
    const int iord = bi & 1;
    const int tid  = threadIdx.x;
    const int lane = tid & 31, warp = tid >> 5;

    __shared__ __align__(16) float xs[64][36];    // [n][k] (pad 4)
    __shared__ __align__(16) float wt[32][128];   // [k][d], XOR-swizzled float4 columns

    const float* xb = x + ((size_t)bi * N_ + nt * 64) * D_;
    const float* Wb = W + (size_t)(iord * 2 + c) * D_ * D_;

    unsigned long long acc[8][2];
#pragma unroll
    for (int r = 0; r < 8; r++) { acc[r][0] = 0ull; acc[r][1] = 0ull; }

    for (int kc = 0; kc < 4; kc++) {
        __syncthreads();
#pragma unroll
        for (int t2 = 0; t2 < 2; t2++) {
            int fid = tid + t2 * 256;
            int s = fid >> 3, kq = fid & 7;
            float4 v = *(const float4*)(xb + (size_t)s * D_ + kc * 32 + kq * 4);
            *(float4*)&xs[s][kq * 4] = v;
        }
#pragma unroll
        for (int t4 = 0; t4 < 4; t4++) {
            int fid = tid + t4 * 256;
            int d = fid >> 3, kq = fid & 7;
            float4 v = *(const float4*)(Wb + (size_t)d * D_ + kc * 32 + kq * 4);
            int d4 = d >> 2, dr = d & 3;
            wt[kq * 4 + 0][((d4 ^ (kq * 4 + 0)) << 2) + dr] = v.x;
            wt[kq * 4 + 1][((d4 ^ (kq * 4 + 1)) << 2) + dr] = v.y;
            wt[kq * 4 + 2][((d4 ^ (kq * 4 + 2)) << 2) + dr] = v.z;
            wt[kq * 4 + 3][((d4 ^ (kq * 4 + 3)) << 2) + dr] = v.w;
        }
        __syncthreads();
#pragma unroll 4
        for (int k = 0; k < 32; k++) {
            float4 wv = *(const float4*)&wt[k][(lane ^ k) << 2];
            unsigned long long w01 = pk2(wv.x, wv.y);
            unsigned long long w23 = pk2(wv.z, wv.w);
#pragma unroll
            for (int r = 0; r < 8; r++) {
                float a = xs[warp * 8 + r][k];
                unsigned long long a2 = pk2(a, a);
                fma2(acc[r][0], a2, w01);
                fma2(acc[r][1], a2, w23);
            }
        }
    }

    const float4 pbv = *(const float4*)(pb + (iord * 2 + c) * D_ + lane * 4);
    const int h  = lane >> 2;
    const int fb = (lane & 3) * 4;
    const float4 av = *(const float4*)(asrc + ((iord * 2 + c) * H_ + h) * DH_ + fb);
    const float4 dv = *(const float4*)(adst + ((iord * 2 + c) * H_ + h) * DH_ + fb);
#pragma unroll
    for (int r = 0; r < 8; r++) {
        int n = nt * 64 + warp * 8 + r;
        float x0, x1, x2, x3;
        upk2(acc[r][0], x0, x1);
        upk2(acc[r][1], x2, x3);
        x0 += pbv.x; x1 += pbv.y; x2 += pbv.z; x3 += pbv.w;
        *(float4*)(g_xp + ((size_t)bic * N_ + n) * D_ + lane * 4) = make_float4(x0, x1, x2, x3);
        float ps = x0 * av.x + x1 * av.y + x2 * av.z + x3 * av.w;
        float pd = x0 * dv.x + x1 * dv.y + x2 * dv.z + x3 * dv.w;
        ps += __shfl_xor_sync(0xffffffffu, ps, 1);
        ps += __shfl_xor_sync(0xffffffffu, ps, 2);
        pd += __shfl_xor_sync(0xffffffffu, pd, 1);
        pd += __shfl_xor_sync(0xffffffffu, pd, 2);
        if ((lane & 3) == 0) {
            size_t o = ((size_t)bic * N_ + n) * H_ + h;
            *(float4*)(g_src4 + o * 4) = make_float4(ps, __expf(ps), __expf(0.2f * ps), 0.0f);
            *(float4*)(g_dst4 + o * 4) = make_float4(pd, __expf(pd), __expf(0.2f * pd), 0.0f);
        }
    }
}

// ============================================================================
// Kernel 2: attention, cp.async double-buffered, MUFU-free, 4-dst blocking,
//           bit-packed edge masks, deduped score computation.
// grid: (4 dst-tiles of 128, 64 bic), block 256.
// Per-buffer float layout: [0,5120) xh(32x160, head-stride 20)
//                          [5120,6144) ss(32x32)  [6144,6272) mask (32 s x 4 u32)
// ============================================================================
#define TS 32
#define BUF_FLOATS 6272

__global__ __launch_bounds__(256, 2) void att_kernel(const float* __restrict__ bias)
{
    extern __shared__ __align__(16) float smem[];
    const int bic  = blockIdx.y;
    const int tile = blockIdx.x;
    const int c    = bic & 1;
    const int bi   = bic >> 1;
    const int iord = bi & 1;
    const int tid  = threadIdx.x;
    const int h    = tid & 7;
    const int dl   = tid >> 3;             // 0..31
    const int dst0 = tile * 128 + dl * 4;  // 4 consecutive dsts
    const int wsel = dl >> 3;              // mask word within the 4 covering this tile
    const int shft = (dl & 7) * 4;         // bit offset of this thread's 4 dsts

    unsigned int sbase;
    asm("{.reg .u64 t; cvta.to.shared.u64 t, %1; cvt.u32.u64 %0, t;}"
        : "=r"(sbase) : "l"(smem));

    const float* xp    = g_xp   + (size_t)bic * N_ * D_;
    const float* src4p = g_src4 + (size_t)bic * N_ * H_ * 4;
    const unsigned int* mgp = g_mask + (size_t)bic * N_ * 16 + tile * 4;

    const int xs_s = tid >> 5, xs_dq = tid & 31;  // +k*8 rows
    const int ss_s = tid >> 3, ss_h = tid & 7;

    float sd[4], q1[4], q2[4], Z[4];
#pragma unroll
    for (int d = 0; d < 4; d++) {
        float4 v = *(const float4*)(g_dst4 + (((size_t)bic * N_ + dst0 + d) * H_ + h) * 4);
        sd[d] = v.x; q1[d] = v.y; q2[d] = v.z; Z[d] = 0.0f;
    }

    unsigned long long acc[4][8];
#pragma unroll
    for (int d = 0; d < 4; d++)
#pragma unroll
        for (int j = 0; j < 8; j++) acc[d][j] = 0ull;

    auto issue = [&](int t, int buf) {
        const int s0 = t * TS;
        const unsigned int b = sbase + buf * (BUF_FLOATS * 4);
#pragma unroll
        for (int k = 0; k < 4; k++) {
            int s = xs_s + k * 8;
            cpa16(b + (unsigned)(s * 640 + (xs_dq >> 2) * 80 + (xs_dq & 3) * 16),
                  xp + (size_t)(s0 + s) * D_ + xs_dq * 4);
        }
        cpa16(b + 20480u + (unsigned)(ss_s * 128 + ss_h * 16),
              src4p + ((size_t)(s0 + ss_s) * H_ + ss_h) * 4);
        if (tid < 32)
            cpa16(b + 24576u + (unsigned)(tid * 16), mgp + (size_t)(s0 + tid) * 16);
        cpa_commit();
    };

    issue(0, 0);

#pragma unroll 1
    for (int t = 0; t < N_ / TS; t++) {
        const int p = t & 1;
        cpa_wait0();
        __syncthreads();
        if (t < N_ / TS - 1) issue(t + 1, 1 - p);

        const float* xhp = smem + p * BUF_FLOATS;
        const float* ssp = xhp + 5120;
        const unsigned int* mkp = (const unsigned int*)(xhp + 6144);
#pragma unroll 4
        for (int s = 0; s < TS; s++) {
            float4 ssv = *(const float4*)(ssp + s * 32 + h * 4);     // {ss, p1, p2, -}
            unsigned int bits = mkp[s * 4 + wsel] >> shft;           // 4 edge bits
            const ulonglong2* xr = (const ulonglong2*)(xhp + s * 160 + h * 20);
            ulonglong2 xA = xr[0], xB = xr[1], xC = xr[2], xD = xr[3];

            float eb4[4];
#pragma unroll
            for (int d = 0; d < 4; d++) {
                float t0 = ssv.x + sd[d];
                bool ge  = (t0 >= 0.0f);
                float pa = ge ? ssv.y : ssv.z;       // exp(ss) or exp(.2 ss)
                float qa = ge ? q1[d] : q2[d];       // exp(sd) or exp(.2 sd)
                float e  = pa * qa;                  // exp(lrelu(ss+sd))
                float eb = (bits & (1u << d)) ? e : 1.0f;  // edge? e : 1
                Z[d] += eb;
                eb4[d] = eb;
            }
#pragma unroll
            for (int d = 0; d < 4; d++) {
                unsigned long long e2 = pk2(eb4[d], eb4[d]);
                fma2(acc[d][0], e2, xA.x);
                fma2(acc[d][1], e2, xA.y);
                fma2(acc[d][2], e2, xB.x);
                fma2(acc[d][3], e2, xB.y);
                fma2(acc[d][4], e2, xC.x);
                fma2(acc[d][5], e2, xC.y);
                fma2(acc[d][6], e2, xD.x);
                fma2(acc[d][7], e2, xD.y);
            }
        }
    }

    // epilogue: /Z, + xp (add_self_loops), + bias
    float4 bq[4];
#pragma unroll
    for (int jj = 0; jj < 4; jj++)
        bq[jj] = *(const float4*)(bias + (iord * 2 + c) * D_ + h * DH_ + jj * 4);
#pragma unroll
    for (int d = 0; d < 4; d++) {
        const float invZ = 1.0f / Z[d];
        const float* xpd  = xp + (size_t)(dst0 + d) * D_ + h * DH_;
        float*       outp = g_att + (size_t)bic * N_ * D_ + (size_t)(dst0 + d) * D_ + h * DH_;
#pragma unroll
        for (int jj = 0; jj < 4; jj++) {
            float f0, f1, f2, f3;
            upk2(acc[d][2 * jj],     f0, f1);
            upk2(acc[d][2 * jj + 1], f2, f3);
            float4 xq = *(const float4*)(xpd + jj * 4);
            float4 o;
            o.x = f0 * invZ + xq.x + bq[jj].x;
            o.y = f1 * invZ + xq.y + bq[jj].y;
            o.z = f2 * invZ + xq.z + bq[jj].z;
            o.w = f3 * invZ + xq.w + bq[jj].w;
            *(float4*)(outp + jj * 4) = o;
        }
    }
}

// ============================================================================
// Kernel 3: combine.  h[b,i] = att[b,i,0] + att[b,i,1];
//           out[b,i] = h[b,i] + 0.5*(h[b,0] + h[b,1])
// ============================================================================
__global__ void combine_kernel(float4* __restrict__ out) {
    int gid = blockIdx.x * blockDim.x + threadIdx.x;   // 0 .. 16*16384-1
    int b = gid >> 14;
    int r = gid & 16383;
    const float4* a = (const float4*)g_att;
    float4 a00 = a[(size_t)(b * 4 + 0) * 16384 + r];
    float4 a01 = a[(size_t)(b * 4 + 1) * 16384 + r];
    float4 a10 = a[(size_t)(b * 4 + 2) * 16384 + r];
    float4 a11 = a[(size_t)(b * 4 + 3) * 16384 + r];
    float4 h0, h1, o0, o1;
    h0.x = a00.x + a01.x; h0.y = a00.y + a01.y; h0.z = a00.z + a01.z; h0.w = a00.w + a01.w;
    h1.x = a10.x + a11.x; h1.y = a10.y + a11.y; h1.z = a10.z + a11.z; h1.w = a10.w + a11.w;
    float mx = 0.5f * (h0.x + h1.x), my = 0.5f * (h0.y + h1.y);
    float mz = 0.5f * (h0.z + h1.z), mw = 0.5f * (h0.w + h1.w);
    o0.x = h0.x + mx; o0.y = h0.y + my; o0.z = h0.z + mz; o0.w = h0.w + mw;
    o1.x = h1.x + mx; o1.y = h1.y + my; o1.z = h1.z + mz; o1.w = h1.w + mw;
    out[(size_t)(b * 2 + 0) * 16384 + r] = o0;
    out[(size_t)(b * 2 + 1) * 16384 + r] = o1;
}

// ============================================================================
extern "C" void kernel_launch(void* const* d_in, const int* in_sizes, int n_in,
                              void* d_out, int out_size) {
    const float* x    = (const float*)d_in[0];
    const int*   A    = (const int*)  d_in[1];
    const float* W    = (const float*)d_in[2];
    const float* pb   = (const float*)d_in[3];
    const float* asrc = (const float*)d_in[4];
    const float* adst = (const float*)d_in[5];
    const float* bias = (const float*)d_in[6];

    cudaFuncSetAttribute(att_kernel, cudaFuncAttributeMaxDynamicSharedMemorySize,
                         2 * BUF_FLOATS * 4);

    mask_kernel<<<32768, 256>>>(A);
    proj_kernel<<<dim3(8, 64), 256>>>(x, W, pb, asrc, adst);
    att_kernel<<<dim3(4, 64), 256, 2 * BUF_FLOATS * 4>>>(bias);
    combine_kernel<<<1024, 256>>>((float4*)d_out);
}

// round 12
// speedup vs baseline: 1.2503x; 1.2337x over previous
#include <cuda_runtime.h>

#define B_ 16
#define ORDER_ 2
#define N_ 512
#define D_ 128
#define H_ 8
#define DH_ 16
#define NBIC 64   // B*ORDER*2 (b,i,c) combos

// ---------------- scratch (device globals; no allocations) ----------------
__device__ __align__(16) float g_xp  [NBIC * N_ * D_];     // projected features (+pb)
__device__ __align__(16) float g_src2[NBIC * N_ * H_ * 2]; // {exp(ssrc), exp(.2 ssrc)}
__device__ __align__(16) float g_dst2[NBIC * N_ * H_ * 2]; // {exp(sdst), exp(.2 sdst)}
__device__ __align__(16) unsigned int g_mask[NBIC * N_ * (N_ / 32)]; // 1 bit/edge
__device__ __align__(16) float g_att [NBIC * N_ * D_];     // per-conv GAT output

// ---------------- helpers ----------------
__device__ __forceinline__ unsigned long long pk2(float a, float b) {
    unsigned long long r;
    asm("mov.b64 %0, {%1, %2};" : "=l"(r) : "r"(__float_as_uint(a)), "r"(__float_as_uint(b)));
    return r;
}
__device__ __forceinline__ void upk2(unsigned long long v, float& a, float& b) {
    unsigned int lo, hi;
    asm("mov.b64 {%0, %1}, %2;" : "=r"(lo), "=r"(hi) : "l"(v));
    a = __uint_as_float(lo); b = __uint_as_float(hi);
}
__device__ __forceinline__ void fma2(unsigned long long& d, unsigned long long a, unsigned long long b) {
    asm("fma.rn.f32x2 %0, %1, %2, %0;" : "+l"(d) : "l"(a), "l"(b));
}
__device__ __forceinline__ void cpa16(unsigned int s, const void* g) {
    asm volatile("cp.async.cg.shared.global [%0], [%1], 16;" :: "r"(s), "l"(g) : "memory");
}
__device__ __forceinline__ void cpa8(unsigned int s, const void* g) {
    asm volatile("cp.async.ca.shared.global [%0], [%1], 8;" :: "r"(s), "l"(g) : "memory");
}
__device__ __forceinline__ void cpa_commit() {
    asm volatile("cp.async.commit_group;" ::: "memory");
}
__device__ __forceinline__ void cpa_wait0() {
    asm volatile("cp.async.wait_group 0;" ::: "memory");
}
__device__ __forceinline__ unsigned int cvt_tf32(float x) {
    unsigned int r; asm("cvt.rna.tf32.f32 %0, %1;" : "=r"(r) : "f"(x)); return r;
}
__device__ __forceinline__ void mma_tf32(float* c,
    unsigned int a0, unsigned int a1, unsigned int a2, unsigned int a3,
    unsigned int b0, unsigned int b1) {
    asm("mma.sync.aligned.m16n8k8.row.col.f32.tf32.tf32.f32 "
        "{%0,%1,%2,%3}, {%4,%5,%6,%7}, {%8,%9}, {%0,%1,%2,%3};"
        : "+f"(c[0]), "+f"(c[1]), "+f"(c[2]), "+f"(c[3])
        : "r"(a0), "r"(a1), "r"(a2), "r"(a3), "r"(b0), "r"(b1));
}

// ============================================================================
// Kernel 0: bit-packed edge masks via ballot.
// ============================================================================
__global__ __launch_bounds__(256) void mask_kernel(const int* __restrict__ A) {
    int gid  = blockIdx.x * 256 + threadIdx.x;
    int lane = gid & 31;
    int wlin = gid >> 5;
    int bi   = wlin >> 13;
    int rr   = wlin & 8191;
    int s    = rr >> 4, w = rr & 15;
    int a = A[((size_t)(bi * N_ + s)) * N_ + w * 32 + lane];
    unsigned int m0 = __ballot_sync(0xffffffffu, a == 4 || a == 2);
    unsigned int m1 = __ballot_sync(0xffffffffu, a == 4 || a == 3);
    if (lane == 0) g_mask[((size_t)(bi * 2 + 0) * N_ + s) * 16 + w] = m0;
    if (lane == 1) g_mask[((size_t)(bi * 2 + 1) * N_ + s) * 16 + w] = m1;
}

// ============================================================================
// Kernel 1: projection xp = x @ W^T + pb, fused head-dot + exp epilogue.
// ============================================================================
__global__ __launch_bounds__(256) void proj_kernel(
    const float* __restrict__ x, const float* __restrict__ W, const float* __restrict__ pb,
    const float* __restrict__ asrc, const float* __restrict__ adst)
{
    const int bic  = blockIdx.y;
    const int nt   = blockIdx.x;
    const int c    = bic & 1;
    const int bi   = bic >> 1;
    const int iord = bi & 1;
    const int tid  = threadIdx.x;
    const int lane = tid & 31, warp = tid >> 5;

    __shared__ __align__(16) float xs[64][36];
    __shared__ __align__(16) float wt[32][128];

    const float* xb = x + ((size_t)bi * N_ + nt * 64) * D_;
    const float* Wb = W + (size_t)(iord * 2 + c) * D_ * D_;

    unsigned long long acc[8][2];
#pragma unroll
    for (int r = 0; r < 8; r++) { acc[r][0] = 0ull; acc[r][1] = 0ull; }

    for (int kc = 0; kc < 4; kc++) {
        __syncthreads();
#pragma unroll
        for (int t2 = 0; t2 < 2; t2++) {
            int fid = tid + t2 * 256;
            int s = fid >> 3, kq = fid & 7;
            float4 v = *(const float4*)(xb + (size_t)s * D_ + kc * 32 + kq * 4);
            *(float4*)&xs[s][kq * 4] = v;
        }
#pragma unroll
        for (int t4 = 0; t4 < 4; t4++) {
            int fid = tid + t4 * 256;
            int d = fid >> 3, kq = fid & 7;
            float4 v = *(const float4*)(Wb + (size_t)d * D_ + kc * 32 + kq * 4);
            int d4 = d >> 2, dr = d & 3;
            wt[kq * 4 + 0][((d4 ^ (kq * 4 + 0)) << 2) + dr] = v.x;
            wt[kq * 4 + 1][((d4 ^ (kq * 4 + 1)) << 2) + dr] = v.y;
            wt[kq * 4 + 2][((d4 ^ (kq * 4 + 2)) << 2) + dr] = v.z;
            wt[kq * 4 + 3][((d4 ^ (kq * 4 + 3)) << 2) + dr] = v.w;
        }
        __syncthreads();
#pragma unroll 4
        for (int k = 0; k < 32; k++) {
            float4 wv = *(const float4*)&wt[k][(lane ^ k) << 2];
            unsigned long long w01 = pk2(wv.x, wv.y);
            unsigned long long w23 = pk2(wv.z, wv.w);
#pragma unroll
            for (int r = 0; r < 8; r++) {
                float a = xs[warp * 8 + r][k];
                unsigned long long a2 = pk2(a, a);
                fma2(acc[r][0], a2, w01);
                fma2(acc[r][1], a2, w23);
            }
        }
    }

    const float4 pbv = *(const float4*)(pb + (iord * 2 + c) * D_ + lane * 4);
    const int h  = lane >> 2;
    const int fb = (lane & 3) * 4;
    const float4 av = *(const float4*)(asrc + ((iord * 2 + c) * H_ + h) * DH_ + fb);
    const float4 dv = *(const float4*)(adst + ((iord * 2 + c) * H_ + h) * DH_ + fb);
#pragma unroll
    for (int r = 0; r < 8; r++) {
        int n = nt * 64 + warp * 8 + r;
        float x0, x1, x2, x3;
        upk2(acc[r][0], x0, x1);
        upk2(acc[r][1], x2, x3);
        x0 += pbv.x; x1 += pbv.y; x2 += pbv.z; x3 += pbv.w;
        *(float4*)(g_xp + ((size_t)bic * N_ + n) * D_ + lane * 4) = make_float4(x0, x1, x2, x3);
        float ps = x0 * av.x + x1 * av.y + x2 * av.z + x3 * av.w;
        float pd = x0 * dv.x + x1 * dv.y + x2 * dv.z + x3 * dv.w;
        ps += __shfl_xor_sync(0xffffffffu, ps, 1);
        ps += __shfl_xor_sync(0xffffffffu, ps, 2);
        pd += __shfl_xor_sync(0xffffffffu, pd, 1);
        pd += __shfl_xor_sync(0xffffffffu, pd, 2);
        if ((lane & 3) == 0) {
            size_t o = ((size_t)bic * N_ + n) * H_ + h;
            *(float2*)(g_src2 + o * 2) = make_float2(__expf(ps), __expf(0.2f * ps));
            *(float2*)(g_dst2 + o * 2) = make_float2(__expf(pd), __expf(0.2f * pd));
        }
    }
}

// ============================================================================
// Kernel 2: attention via mma.sync tf32. grid (4 dtiles x 64 bic), 256 thr.
// warp = head; 8 m-tiles (16 dst) x 2 n-tiles (8 feat); K = 512 src.
// A-frag (attention weights) built in registers:
//   e = max(p1*q1, p2*q2)  [= exp(lrelu(ss+sd))],  eb = edgebit ? e : 1
// Z accumulated in fp32 alongside; quad shfl-reduce at end.
// Dyn smem floats: sd[128][9] float2 (2304) ; 2 x buf{ xh[32][136]=4352,
//   ss[32][9] float2 = 576, mask 32x16B = 128 } = 5056 each.
// ============================================================================
#define TS 32
#define SD_F 2304
#define BUF_F 5056
#define SMEM_BYTES ((SD_F + 2 * BUF_F) * 4)

__global__ __launch_bounds__(256, 2) void att_kernel(const float* __restrict__ bias)
{
    extern __shared__ __align__(16) float smem[];
    const int bic  = blockIdx.y;
    const int tile = blockIdx.x;
    const int c    = bic & 1;
    const int bi   = bic >> 1;
    const int iord = bi & 1;
    const int tid  = threadIdx.x;
    const int lane = tid & 31;
    const int h    = tid >> 5;           // warp = head
    const int row  = lane >> 2;          // 0..7 (mma group id)
    const int qid  = lane & 3;           // 0..3

    unsigned int sbase;
    asm("{.reg .u64 t; cvta.to.shared.u64 t, %1; cvt.u32.u64 %0, t;}"
        : "=r"(sbase) : "l"(smem));

    const float* xp    = g_xp   + (size_t)bic * N_ * D_;
    const float* src2p = g_src2 + (size_t)bic * N_ * H_ * 2;
    const float* dst2p = g_dst2 + (size_t)bic * N_ * H_ * 2;
    const unsigned int* mgp = g_mask + (size_t)bic * N_ * 16 + tile * 4;

    // fill-thread mapping
    const int xs_s = tid >> 5, xs_fq = tid & 31;   // xh: +k*8 rows of 32 float4
    const int ss_s = tid >> 3, ss_h = tid & 7;     // ss/sd: (s|d, h)

    float c_[8][2][4];
    float z_[8][2];
#pragma unroll
    for (int m = 0; m < 8; m++) {
        z_[m][0] = 0.0f; z_[m][1] = 0.0f;
#pragma unroll
        for (int j = 0; j < 2; j++)
#pragma unroll
            for (int k = 0; k < 4; k++) c_[m][j][k] = 0.0f;
    }

    auto issue = [&](int t, int buf) {
        const int s0 = t * TS;
        const unsigned int b = sbase + (SD_F + buf * BUF_F) * 4;
#pragma unroll
        for (int k = 0; k < 4; k++) {
            int s = xs_s + k * 8;
            cpa16(b + (unsigned)(s * 544 + xs_fq * 16),
                  xp + (size_t)(s0 + s) * D_ + xs_fq * 4);
        }
        cpa8(b + 17408u + (unsigned)((ss_s * 9 + ss_h) * 8),
             src2p + ((size_t)(s0 + ss_s) * H_ + ss_h) * 2);
        if (tid < 32)
            cpa16(b + 19712u + (unsigned)(tid * 16), mgp + (size_t)(s0 + tid) * 16);
        cpa_commit();
    };

    // preload sd (128 dst x 8 h float2) + first tile
    {
#pragma unroll
        for (int k = 0; k < 4; k++) {
            int idx = tid + k * 256;
            int d = idx >> 3, hh = idx & 7;
            cpa8(sbase + (unsigned)((d * 9 + hh) * 8),
                 dst2p + ((size_t)(tile * 128 + d) * H_ + hh) * 2);
        }
        issue(0, 0);
    }

    const float* sdp = smem;   // [d][9] float2

#pragma unroll 1
    for (int t = 0; t < N_ / TS; t++) {
        const int p = t & 1;
        cpa_wait0();
        __syncthreads();
        if (t < N_ / TS - 1) issue(t + 1, 1 - p);

        const float* xhp = smem + SD_F + p * BUF_F;        // [s][136]
        const float* ssp = xhp + 4352;                     // [s][9] float2
        const unsigned int* mkp = (const unsigned int*)(ssp + 576); // [s][4]

#pragma unroll
        for (int kc = 0; kc < 4; kc++) {
            const int s_lo = kc * 8 + qid;
            const int s_hi = s_lo + 4;
            float2 pA = *(const float2*)(ssp + (s_lo * 9 + h) * 2);
            float2 pB = *(const float2*)(ssp + (s_hi * 9 + h) * 2);
            uint4 mA = *(const uint4*)(mkp + s_lo * 4);
            uint4 mB = *(const uint4*)(mkp + s_hi * 4);
            // B fragments (features for this head)
            unsigned int b0[2], b1[2];
#pragma unroll
            for (int j = 0; j < 2; j++) {
                int f = h * 16 + j * 8 + row;
                b0[j] = cvt_tf32(xhp[s_lo * 136 + f]);
                b1[j] = cvt_tf32(xhp[s_hi * 136 + f]);
            }
#pragma unroll
            for (int m = 0; m < 8; m++) {
                float2 qA = *(const float2*)(sdp + ((m * 16 + row) * 9 + h) * 2);
                float2 qB = *(const float2*)(sdp + ((m * 16 + row + 8) * 9 + h) * 2);
                unsigned int mwA, mwB;
                switch (m >> 1) {
                    case 0: mwA = mA.x; mwB = mB.x; break;
                    case 1: mwA = mA.y; mwB = mB.y; break;
                    case 2: mwA = mA.z; mwB = mB.z; break;
                    default: mwA = mA.w; mwB = mB.w; break;
                }
                const int sh = ((m & 1) << 4) + row;
                float e00 = fmaxf(pA.x * qA.x, pA.y * qA.y);   // (d, s_lo)
                float e10 = fmaxf(pA.x * qB.x, pA.y * qB.y);   // (d+8, s_lo)
                float e01 = fmaxf(pB.x * qA.x, pB.y * qA.y);   // (d, s_hi)
                float e11 = fmaxf(pB.x * qB.x, pB.y * qB.y);   // (d+8, s_hi)
                float a0f = ((mwA >> sh) & 1u)       ? e00 : 1.0f;
                float a1f = ((mwA >> (sh + 8)) & 1u) ? e10 : 1.0f;
                float a2f = ((mwB >> sh) & 1u)       ? e01 : 1.0f;
                float a3f = ((mwB >> (sh + 8)) & 1u) ? e11 : 1.0f;
                z_[m][0] += a0f + a2f;
                z_[m][1] += a1f + a3f;
                unsigned int a0 = cvt_tf32(a0f), a1 = cvt_tf32(a1f);
                unsigned int a2 = cvt_tf32(a2f), a3 = cvt_tf32(a3f);
                mma_tf32(c_[m][0], a0, a1, a2, a3, b0[0], b1[0]);
                mma_tf32(c_[m][1], a0, a1, a2, a3, b0[1], b1[1]);
            }
        }
    }

    // epilogue: reduce Z over quad, /Z, +xp, +bias, store
    const float* biasp = bias + (iord * 2 + c) * D_;
#pragma unroll
    for (int m = 0; m < 8; m++) {
        float z0 = z_[m][0];
        z0 += __shfl_xor_sync(0xffffffffu, z0, 1);
        z0 += __shfl_xor_sync(0xffffffffu, z0, 2);
        float z1 = z_[m][1];
        z1 += __shfl_xor_sync(0xffffffffu, z1, 1);
        z1 += __shfl_xor_sync(0xffffffffu, z1, 2);
        const float i0 = 1.0f / z0, i1 = 1.0f / z1;
        const int dA = tile * 128 + m * 16 + row;
        const int dB = dA + 8;
#pragma unroll
        for (int j = 0; j < 2; j++) {
            const int f = h * 16 + j * 8 + 2 * qid;
            float2 xA = *(const float2*)(xp + (size_t)dA * D_ + f);
            float2 xB = *(const float2*)(xp + (size_t)dB * D_ + f);
            float2 bb = *(const float2*)(biasp + f);
            float2 oA, oB;
            oA.x = c_[m][j][0] * i0 + xA.x + bb.x;
            oA.y = c_[m][j][1] * i0 + xA.y + bb.y;
            oB.x = c_[m][j][2] * i1 + xB.x + bb.x;
            oB.y = c_[m][j][3] * i1 + xB.y + bb.y;
            *(float2*)(g_att + ((size_t)bic * N_ + dA) * D_ + f) = oA;
            *(float2*)(g_att + ((size_t)bic * N_ + dB) * D_ + f) = oB;
        }
    }
}

// ============================================================================
// Kernel 3: combine.
// ============================================================================
__global__ void combine_kernel(float4* __restrict__ out) {
    int gid = blockIdx.x * blockDim.x + threadIdx.x;
    int b = gid >> 14;
    int r = gid & 16383;
    const float4* a = (const float4*)g_att;
    float4 a00 = a[(size_t)(b * 4 + 0) * 16384 + r];
    float4 a01 = a[(size_t)(b * 4 + 1) * 16384 + r];
    float4 a10 = a[(size_t)(b * 4 + 2) * 16384 + r];
    float4 a11 = a[(size_t)(b * 4 + 3) * 16384 + r];
    float4 h0, h1, o0, o1;
    h0.x = a00.x + a01.x; h0.y = a00.y + a01.y; h0.z = a00.z + a01.z; h0.w = a00.w + a01.w;
    h1.x = a10.x + a11.x; h1.y = a10.y + a11.y; h1.z = a10.z + a11.z; h1.w = a10.w + a11.w;
    float mx = 0.5f * (h0.x + h1.x), my = 0.5f * (h0.y + h1.y);
    float mz = 0.5f * (h0.z + h1.z), mw = 0.5f * (h0.w + h1.w);
    o0.x = h0.x + mx; o0.y = h0.y + my; o0.z = h0.z + mz; o0.w = h0.w + mw;
    o1.x = h1.x + mx; o1.y = h1.y + my; o1.z = h1.z + mz; o1.w = h1.w + mw;
    out[(size_t)(b * 2 + 0) * 16384 + r] = o0;
    out[(size_t)(b * 2 + 1) * 16384 + r] = o1;
}

// ============================================================================
extern "C" void kernel_launch(void* const* d_in, const int* in_sizes, int n_in,
                              void* d_out, int out_size) {
    const float* x    = (const float*)d_in[0];
    const int*   A    = (const int*)  d_in[1];
    const float* W    = (const float*)d_in[2];
    const float* pb   = (const float*)d_in[3];
    const float* asrc = (const float*)d_in[4];
    const float* adst = (const float*)d_in[5];
    const float* bias = (const float*)d_in[6];

    cudaFuncSetAttribute(att_kernel, cudaFuncAttributeMaxDynamicSharedMemorySize,
                         SMEM_BYTES);

    mask_kernel<<<32768, 256>>>(A);
    proj_kernel<<<dim3(8, 64), 256>>>(x, W, pb, asrc, adst);
    att_kernel<<<dim3(4, 64), 256, SMEM_BYTES>>>(bias);
    combine_kernel<<<1024, 256>>>((float4*)d_out);
}

// round 14
// speedup vs baseline: 1.4611x; 1.1686x over previous
#include <cuda_runtime.h>

#define B_ 16
#define ORDER_ 2
#define N_ 512
#define D_ 128
#define H_ 8
#define DH_ 16
#define NBIC 64   // B*ORDER*2 (b,i,c) combos

// ---------------- scratch (device globals; no allocations) ----------------
__device__ __align__(16) float g_xp  [NBIC * N_ * D_];     // projected features (+pb)
__device__ __align__(16) float g_src2[NBIC * N_ * H_ * 2]; // {exp(ssrc), exp(.2 ssrc)}
__device__ __align__(16) float g_dst2[NBIC * N_ * H_ * 2]; // {exp(sdst), exp(.2 sdst)}
__device__ __align__(16) unsigned int g_mask[NBIC * N_ * (N_ / 32)]; // 1 bit/edge
__device__ __align__(16) float g_att [NBIC * N_ * D_];     // per-conv GAT output

// ---------------- helpers ----------------
__device__ __forceinline__ void cpa16(unsigned int s, const void* g) {
    asm volatile("cp.async.cg.shared.global [%0], [%1], 16;" :: "r"(s), "l"(g) : "memory");
}
__device__ __forceinline__ void cpa8(unsigned int s, const void* g) {
    asm volatile("cp.async.ca.shared.global [%0], [%1], 8;" :: "r"(s), "l"(g) : "memory");
}
__device__ __forceinline__ void cpa_commit() {
    asm volatile("cp.async.commit_group;" ::: "memory");
}
__device__ __forceinline__ void cpa_wait0() {
    asm volatile("cp.async.wait_group 0;" ::: "memory");
}
__device__ __forceinline__ unsigned int cvt_tf32(float x) {
    unsigned int r; asm("cvt.rna.tf32.f32 %0, %1;" : "=r"(r) : "f"(x)); return r;
}
__device__ __forceinline__ void mma_tf32(float* c,
    unsigned int a0, unsigned int a1, unsigned int a2, unsigned int a3,
    unsigned int b0, unsigned int b1) {
    asm("mma.sync.aligned.m16n8k8.row.col.f32.tf32.tf32.f32 "
        "{%0,%1,%2,%3}, {%4,%5,%6,%7}, {%8,%9}, {%0,%1,%2,%3};"
        : "+f"(c[0]), "+f"(c[1]), "+f"(c[2]), "+f"(c[3])
        : "r"(a0), "r"(a1), "r"(a2), "r"(a3), "r"(b0), "r"(b1));
}
__device__ __forceinline__ unsigned int smem_u32(const void* p) {
    unsigned int r;
    asm("{.reg .u64 t; cvta.to.shared.u64 t, %1; cvt.u32.u64 %0, t;}" : "=r"(r) : "l"(p));
    return r;
}

// ============================================================================
// Kernel 0: bit-packed edge masks via ballot.
// ============================================================================
__global__ __launch_bounds__(256) void mask_kernel(const int* __restrict__ A) {
    int gid  = blockIdx.x * 256 + threadIdx.x;
    int lane = gid & 31;
    int wlin = gid >> 5;
    int bi   = wlin >> 13;
    int rr   = wlin & 8191;
    int s    = rr >> 4, w = rr & 15;
    int a = A[((size_t)(bi * N_ + s)) * N_ + w * 32 + lane];
    unsigned int m0 = __ballot_sync(0xffffffffu, a == 4 || a == 2);
    unsigned int m1 = __ballot_sync(0xffffffffu, a == 4 || a == 3);
    if (lane == 0) g_mask[((size_t)(bi * 2 + 0) * N_ + s) * 16 + w] = m0;
    if (lane == 1) g_mask[((size_t)(bi * 2 + 1) * N_ + s) * 16 + w] = m1;
}

// ============================================================================
// Kernel 1: projection xp = x @ W^T + pb via 3xTF32 mma (fp32-accurate).
// grid (4 mtiles x 64 bic), 256 thr (8 warps = 4m x 2n).
// Warp tile: 32 rows x 64 douts, K=128 in 4 chunks of 32, double-buffered.
// smem/stage: x[128][36] + W[128][36] (both [row][k], pad 4).
// ============================================================================
#define PJ_STAGE_F (128 * 36)
#define PJ_BUF_F (2 * 128 * 36)
#define PJ_SMEM_BYTES (2 * PJ_BUF_F * 4)   // 73728

__global__ __launch_bounds__(256, 2) void proj_kernel(
    const float* __restrict__ x, const float* __restrict__ W, const float* __restrict__ pb)
{
    extern __shared__ __align__(16) float smem[];
    const int bic = blockIdx.y;
    const int mt  = blockIdx.x;
    const int c    = bic & 1;
    const int bi   = bic >> 1;
    const int iord = bi & 1;
    const int tid  = threadIdx.x;
    const int lane = tid & 31, warp = tid >> 5;
    const int wm = warp & 3, wn = warp >> 2;
    const int g  = lane >> 2, tg = lane & 3;

    const unsigned int sbase = smem_u32(smem);
    const float* xb = x + ((size_t)bi * N_ + mt * 128) * D_;
    const float* Wb = W + (size_t)(iord * 2 + c) * D_ * D_;

    auto issue = [&](int kc, int buf) {
        const unsigned int bb = sbase + (unsigned)(buf * PJ_BUF_F * 4);
#pragma unroll
        for (int j = 0; j < 4; j++) {
            int idx = tid + j * 256;
            int r = idx >> 3, kq = idx & 7;
            cpa16(bb + (unsigned)((r * 36 + kq * 4) * 4),
                  xb + (size_t)r * D_ + kc * 32 + kq * 4);
            cpa16(bb + (unsigned)((PJ_STAGE_F + r * 36 + kq * 4) * 4),
                  Wb + (size_t)r * D_ + kc * 32 + kq * 4);
        }
        cpa_commit();
    };

    float c_[2][8][4];
#pragma unroll
    for (int f = 0; f < 2; f++)
#pragma unroll
        for (int n = 0; n < 8; n++)
#pragma unroll
            for (int k = 0; k < 4; k++) c_[f][n][k] = 0.0f;

    issue(0, 0);

#pragma unroll 1
    for (int kc = 0; kc < 4; kc++) {
        cpa_wait0();
        __syncthreads();
        if (kc < 3) issue(kc + 1, (kc + 1) & 1);
        const float* xs = smem + (kc & 1) * PJ_BUF_F;
        const float* ws = xs + PJ_STAGE_F;

#pragma unroll
        for (int k8 = 0; k8 < 4; k8++) {
            const int k = k8 * 8;
            // A fragments (x rows), hi/lo tf32 split
            unsigned int ah[2][4], al[2][4];
#pragma unroll
            for (int f = 0; f < 2; f++) {
                const int r0 = wm * 32 + f * 16 + g;
                float v0 = xs[(r0)     * 36 + k + tg];
                float v1 = xs[(r0 + 8) * 36 + k + tg];
                float v2 = xs[(r0)     * 36 + k + tg + 4];
                float v3 = xs[(r0 + 8) * 36 + k + tg + 4];
                ah[f][0] = cvt_tf32(v0); al[f][0] = cvt_tf32(v0 - __uint_as_float(ah[f][0]));
                ah[f][1] = cvt_tf32(v1); al[f][1] = cvt_tf32(v1 - __uint_as_float(ah[f][1]));
                ah[f][2] = cvt_tf32(v2); al[f][2] = cvt_tf32(v2 - __uint_as_float(ah[f][2]));
                ah[f][3] = cvt_tf32(v3); al[f][3] = cvt_tf32(v3 - __uint_as_float(ah[f][3]));
            }
#pragma unroll
            for (int n = 0; n < 8; n++) {
                const int dr = wn * 64 + n * 8 + g;
                float b0f = ws[dr * 36 + k + tg];
                float b1f = ws[dr * 36 + k + tg + 4];
                unsigned int bh0 = cvt_tf32(b0f), bh1 = cvt_tf32(b1f);
                unsigned int bl0 = cvt_tf32(b0f - __uint_as_float(bh0));
                unsigned int bl1 = cvt_tf32(b1f - __uint_as_float(bh1));
#pragma unroll
                for (int f = 0; f < 2; f++) {
                    mma_tf32(c_[f][n], ah[f][0], ah[f][1], ah[f][2], ah[f][3], bh0, bh1);
                    mma_tf32(c_[f][n], ah[f][0], ah[f][1], ah[f][2], ah[f][3], bl0, bl1);
                    mma_tf32(c_[f][n], al[f][0], al[f][1], al[f][2], al[f][3], bh0, bh1);
                }
            }
        }
    }

    // epilogue: + pb, store xp
    const float* pbp = pb + (iord * 2 + c) * D_;
#pragma unroll
    for (int n = 0; n < 8; n++) {
        const int dout = wn * 64 + n * 8 + 2 * tg;
        float2 pbv = *(const float2*)(pbp + dout);
#pragma unroll
        for (int f = 0; f < 2; f++) {
            const int r0 = mt * 128 + wm * 32 + f * 16 + g;
            float2 o0, o1;
            o0.x = c_[f][n][0] + pbv.x; o0.y = c_[f][n][1] + pbv.y;
            o1.x = c_[f][n][2] + pbv.x; o1.y = c_[f][n][3] + pbv.y;
            *(float2*)(g_xp + ((size_t)bic * N_ + r0)     * D_ + dout) = o0;
            *(float2*)(g_xp + ((size_t)bic * N_ + r0 + 8) * D_ + dout) = o1;
        }
    }
}

// ============================================================================
// Kernel 1b: per-(node,head) scores + exp forms from g_xp.
// ============================================================================
__global__ __launch_bounds__(256) void score_kernel(
    const float* __restrict__ asrc, const float* __restrict__ adst)
{
    int gid = blockIdx.x * 256 + threadIdx.x;   // 64*512*8
    int h = gid & 7;
    int n = (gid >> 3) & 511;
    int bic = gid >> 12;
    int c = bic & 1, iord = (bic >> 1) & 1;
    const float* xph = g_xp + ((size_t)bic * N_ + n) * D_ + h * DH_;
    const float* av = asrc + ((iord * 2 + c) * H_ + h) * DH_;
    const float* dv = adst + ((iord * 2 + c) * H_ + h) * DH_;
    float ps = 0.0f, pd = 0.0f;
#pragma unroll
    for (int j = 0; j < 4; j++) {
        float4 xv = *(const float4*)(xph + j * 4);
        float4 a4 = *(const float4*)(av + j * 4);
        float4 d4 = *(const float4*)(dv + j * 4);
        ps += xv.x * a4.x + xv.y * a4.y + xv.z * a4.z + xv.w * a4.w;
        pd += xv.x * d4.x + xv.y * d4.y + xv.z * d4.z + xv.w * d4.w;
    }
    size_t o = ((size_t)bic * N_ + n) * H_ + h;
    *(float2*)(g_src2 + o * 2) = make_float2(__expf(ps), __expf(0.2f * ps));
    *(float2*)(g_dst2 + o * 2) = make_float2(__expf(pd), __expf(0.2f * pd));
}

// ============================================================================
// Kernel 2: attention via mma tf32; 64-dst tiles, sd hoisted to registers.
// grid (8 dtiles x 64 bic), 256 thr, warp = head; 4 m-tiles x 2 n-frags, K=512.
// smem floats: sd 64x9 float2 (1152); 2 x buf{ xh 32x136 = 4352,
//   ss 32x9 float2 = 576, mask 32 x uint2 = 64 } = 4992.
// ============================================================================
#define TS 32
#define SD_F 1152
#define BUF_F 4992
#define ATT_SMEM_BYTES ((SD_F + 2 * BUF_F) * 4)

__global__ __launch_bounds__(256, 2) void att_kernel(const float* __restrict__ bias)
{
    extern __shared__ __align__(16) float smem[];
    const int bic  = blockIdx.y;
    const int tile = blockIdx.x;
    const int c    = bic & 1;
    const int bi   = bic >> 1;
    const int iord = bi & 1;
    const int tid  = threadIdx.x;
    const int lane = tid & 31;
    const int h    = tid >> 5;           // warp = head
    const int row  = lane >> 2;          // mma group id
    const int qid  = lane & 3;

    const unsigned int sbase = smem_u32(smem);
    const float* xp    = g_xp   + (size_t)bic * N_ * D_;
    const float* src2p = g_src2 + (size_t)bic * N_ * H_ * 2;
    const float* dst2p = g_dst2 + (size_t)bic * N_ * H_ * 2;
    const unsigned int* mgp = g_mask + (size_t)bic * N_ * 16 + tile * 2;

    const int xs_s = tid >> 5, xs_fq = tid & 31;
    const int ss_s = tid >> 3, ss_h = tid & 7;

    auto issue = [&](int t, int buf) {
        const int s0 = t * TS;
        const unsigned int b = sbase + (SD_F + buf * BUF_F) * 4;
#pragma unroll
        for (int k = 0; k < 4; k++) {
            int s = xs_s + k * 8;
            cpa16(b + (unsigned)(s * 544 + xs_fq * 16),
                  xp + (size_t)(s0 + s) * D_ + xs_fq * 4);
        }
        cpa8(b + 17408u + (unsigned)((ss_s * 9 + ss_h) * 8),
             src2p + ((size_t)(s0 + ss_s) * H_ + ss_h) * 2);
        if (tid < 32)
            cpa8(b + 19712u + (unsigned)(tid * 8), mgp + (size_t)(s0 + tid) * 16);
        cpa_commit();
    };

    // preload sd (64 dst x 8 h float2) + first tile
#pragma unroll
    for (int k = 0; k < 2; k++) {
        int idx = tid + k * 256;
        int d = idx >> 3, hh = idx & 7;
        cpa8(sbase + (unsigned)((d * 9 + hh) * 8),
             dst2p + ((size_t)(tile * 64 + d) * H_ + hh) * 2);
    }
    issue(0, 0);
    cpa_wait0();
    __syncthreads();

    // hoist destination-side exp pairs into registers
    float2 qA[4], qB[4];
#pragma unroll
    for (int m = 0; m < 4; m++) {
        qA[m] = *(const float2*)(smem + ((m * 16 + row) * 9 + h) * 2);
        qB[m] = *(const float2*)(smem + ((m * 16 + row + 8) * 9 + h) * 2);
    }

    float c_[4][2][4];
    float z_[4][2];
#pragma unroll
    for (int m = 0; m < 4; m++) {
        z_[m][0] = 0.0f; z_[m][1] = 0.0f;
#pragma unroll
        for (int j = 0; j < 2; j++)
#pragma unroll
            for (int k = 0; k < 4; k++) c_[m][j][k] = 0.0f;
    }

    issue(1, 1);

#pragma unroll 1
    for (int t = 0; t < N_ / TS; t++) {
        const int p = t & 1;
        if (t > 0) {
            cpa_wait0();
            __syncthreads();
            if (t < N_ / TS - 1) issue(t + 1, 1 - p);
        }

        const float* xhp = smem + SD_F + p * BUF_F;
        const float* ssp = xhp + 4352;
        const unsigned int* mkp = (const unsigned int*)(ssp + 576);

#pragma unroll
        for (int kc = 0; kc < 4; kc++) {
            const int s_lo = kc * 8 + qid;
            const int s_hi = s_lo + 4;
            float2 pA = *(const float2*)(ssp + (s_lo * 9 + h) * 2);
            float2 pB = *(const float2*)(ssp + (s_hi * 9 + h) * 2);
            uint2 mA2 = *(const uint2*)(mkp + s_lo * 2);
            uint2 mB2 = *(const uint2*)(mkp + s_hi * 2);
            unsigned int b0[2], b1[2];
#pragma unroll
            for (int j = 0; j < 2; j++) {
                int f = h * 16 + j * 8 + row;
                b0[j] = cvt_tf32(xhp[s_lo * 136 + f]);
                b1[j] = cvt_tf32(xhp[s_hi * 136 + f]);
            }
#pragma unroll
            for (int m = 0; m < 4; m++) {
                const unsigned int mwA = (m < 2) ? mA2.x : mA2.y;
                const unsigned int mwB = (m < 2) ? mB2.x : mB2.y;
                const int sh = ((m & 1) << 4) + row;
                float e00 = fmaxf(pA.x * qA[m].x, pA.y * qA[m].y);
                float e10 = fmaxf(pA.x * qB[m].x, pA.y * qB[m].y);
                float e01 = fmaxf(pB.x * qA[m].x, pB.y * qA[m].y);
                float e11 = fmaxf(pB.x * qB[m].x, pB.y * qB[m].y);
                float a0f = ((mwA >> sh) & 1u)       ? e00 : 1.0f;
                float a1f = ((mwA >> (sh + 8)) & 1u) ? e10 : 1.0f;
                float a2f = ((mwB >> sh) & 1u)       ? e01 : 1.0f;
                float a3f = ((mwB >> (sh + 8)) & 1u) ? e11 : 1.0f;
                z_[m][0] += a0f + a2f;
                z_[m][1] += a1f + a3f;
                unsigned int a0 = cvt_tf32(a0f), a1 = cvt_tf32(a1f);
                unsigned int a2 = cvt_tf32(a2f), a3 = cvt_tf32(a3f);
                mma_tf32(c_[m][0], a0, a1, a2, a3, b0[0], b1[0]);
                mma_tf32(c_[m][1], a0, a1, a2, a3, b0[1], b1[1]);
            }
        }
    }

    // epilogue: reduce Z over quad, /Z, +xp, +bias, store
    const float* biasp = bias + (iord * 2 + c) * D_;
#pragma unroll
    for (int m = 0; m < 4; m++) {
        float z0 = z_[m][0];
        z0 += __shfl_xor_sync(0xffffffffu, z0, 1);
        z0 += __shfl_xor_sync(0xffffffffu, z0, 2);
        float z1 = z_[m][1];
        z1 += __shfl_xor_sync(0xffffffffu, z1, 1);
        z1 += __shfl_xor_sync(0xffffffffu, z1, 2);
        const float i0 = 1.0f / z0, i1 = 1.0f / z1;
        const int dA = tile * 64 + m * 16 + row;
        const int dB = dA + 8;
#pragma unroll
        for (int j = 0; j < 2; j++) {
            const int f = h * 16 + j * 8 + 2 * qid;
            float2 xA = *(const float2*)(xp + (size_t)dA * D_ + f);
            float2 xB = *(const float2*)(xp + (size_t)dB * D_ + f);
            float2 bb = *(const float2*)(biasp + f);
            float2 oA, oB;
            oA.x = c_[m][j][0] * i0 + xA.x + bb.x;
            oA.y = c_[m][j][1] * i0 + xA.y + bb.y;
            oB.x = c_[m][j][2] * i1 + xB.x + bb.x;
            oB.y = c_[m][j][3] * i1 + xB.y + bb.y;
            *(float2*)(g_att + ((size_t)bic * N_ + dA) * D_ + f) = oA;
            *(float2*)(g_att + ((size_t)bic * N_ + dB) * D_ + f) = oB;
        }
    }
}

// ============================================================================
// Kernel 3: combine.
// ============================================================================
__global__ void combine_kernel(float4* __restrict__ out) {
    int gid = blockIdx.x * blockDim.x + threadIdx.x;
    int b = gid >> 14;
    int r = gid & 16383;
    const float4* a = (const float4*)g_att;
    float4 a00 = a[(size_t)(b * 4 + 0) * 16384 + r];
    float4 a01 = a[(size_t)(b * 4 + 1) * 16384 + r];
    float4 a10 = a[(size_t)(b * 4 + 2) * 16384 + r];
    float4 a11 = a[(size_t)(b * 4 + 3) * 16384 + r];
    float4 h0, h1, o0, o1;
    h0.x = a00.x + a01.x; h0.y = a00.y + a01.y; h0.z = a00.z + a01.z; h0.w = a00.w + a01.w;
    h1.x = a10.x + a11.x; h1.y = a10.y + a11.y; h1.z = a10.z + a11.z; h1.w = a10.w + a11.w;
    float mx = 0.5f * (h0.x + h1.x), my = 0.5f * (h0.y + h1.y);
    float mz = 0.5f * (h0.z + h1.z), mw = 0.5f * (h0.w + h1.w);
    o0.x = h0.x + mx; o0.y = h0.y + my; o0.z = h0.z + mz; o0.w = h0.w + mw;
    o1.x = h1.x + mx; o1.y = h1.y + my; o1.z = h1.z + mz; o1.w = h1.w + mw;
    out[(size_t)(b * 2 + 0) * 16384 + r] = o0;
    out[(size_t)(b * 2 + 1) * 16384 + r] = o1;
}

// ============================================================================
extern "C" void kernel_launch(void* const* d_in, const int* in_sizes, int n_in,
                              void* d_out, int out_size) {
    const float* x    = (const float*)d_in[0];
    const int*   A    = (const int*)  d_in[1];
    const float* W    = (const float*)d_in[2];
    const float* pb   = (const float*)d_in[3];
    const float* asrc = (const float*)d_in[4];
    const float* adst = (const float*)d_in[5];
    const float* bias = (const float*)d_in[6];

    cudaFuncSetAttribute(proj_kernel, cudaFuncAttributeMaxDynamicSharedMemorySize,
                         PJ_SMEM_BYTES);
    cudaFuncSetAttribute(att_kernel, cudaFuncAttributeMaxDynamicSharedMemorySize,
                         ATT_SMEM_BYTES);

    mask_kernel<<<32768, 256>>>(A);
    proj_kernel<<<dim3(4, 64), 256, PJ_SMEM_BYTES>>>(x, W, pb);
    score_kernel<<<1024, 256>>>(asrc, adst);
    att_kernel<<<dim3(8, 64), 256, ATT_SMEM_BYTES>>>(bias);
    combine_kernel<<<1024, 256>>>((float4*)d_out);
}

// round 15
// speedup vs baseline: 1.5092x; 1.0329x over previous
#include <cuda_runtime.h>

#define B_ 16
#define ORDER_ 2
#define N_ 512
#define D_ 128
#define H_ 8
#define DH_ 16
#define NBIC 64   // B*ORDER*2 (b,i,c) combos

// ---------------- scratch (device globals; no allocations) ----------------
__device__ __align__(16) float g_xp  [NBIC * N_ * D_];     // projected features (+pb)
__device__ __align__(16) float g_src2[NBIC * N_ * H_ * 2]; // {exp(ssrc), exp(.2 ssrc)}
__device__ __align__(16) float g_dst2[NBIC * N_ * H_ * 2]; // {exp(sdst), exp(.2 sdst)}
__device__ __align__(16) unsigned int g_mask[NBIC * N_ * (N_ / 32)]; // 1 bit/edge
__device__ __align__(16) float g_att [NBIC * N_ * D_];     // per-conv GAT output

#define TF32_TRUNC 0xFFFFE000u
#define ONE_BITS   0x3F800000u

// ---------------- helpers ----------------
__device__ __forceinline__ void cpa16(unsigned int s, const void* g) {
    asm volatile("cp.async.cg.shared.global [%0], [%1], 16;" :: "r"(s), "l"(g) : "memory");
}
__device__ __forceinline__ void cpa8(unsigned int s, const void* g) {
    asm volatile("cp.async.ca.shared.global [%0], [%1], 8;" :: "r"(s), "l"(g) : "memory");
}
__device__ __forceinline__ void cpa_commit() {
    asm volatile("cp.async.commit_group;" ::: "memory");
}
__device__ __forceinline__ void cpa_wait0() {
    asm volatile("cp.async.wait_group 0;" ::: "memory");
}
__device__ __forceinline__ void mma_tf32(float* c,
    unsigned int a0, unsigned int a1, unsigned int a2, unsigned int a3,
    unsigned int b0, unsigned int b1) {
    asm("mma.sync.aligned.m16n8k8.row.col.f32.tf32.tf32.f32 "
        "{%0,%1,%2,%3}, {%4,%5,%6,%7}, {%8,%9}, {%0,%1,%2,%3};"
        : "+f"(c[0]), "+f"(c[1]), "+f"(c[2]), "+f"(c[3])
        : "r"(a0), "r"(a1), "r"(a2), "r"(a3), "r"(b0), "r"(b1));
}
__device__ __forceinline__ unsigned int smem_u32(const void* p) {
    unsigned int r;
    asm("{.reg .u64 t; cvta.to.shared.u64 t, %1; cvt.u32.u64 %0, t;}" : "=r"(r) : "l"(p));
    return r;
}
// truncation-based tf32 hi/lo split (LOP3 only, no F2FP)
__device__ __forceinline__ void tf32_split(float v, unsigned int& hi, unsigned int& lo) {
    hi = __float_as_uint(v) & TF32_TRUNC;
    lo = __float_as_uint(v - __uint_as_float(hi)) & TF32_TRUNC;
}

// ============================================================================
// Kernel 0: bit-packed edge masks via ballot.
// ============================================================================
__global__ __launch_bounds__(256) void mask_kernel(const int* __restrict__ A) {
    int gid  = blockIdx.x * 256 + threadIdx.x;
    int lane = gid & 31;
    int wlin = gid >> 5;
    int bi   = wlin >> 13;
    int rr   = wlin & 8191;
    int s    = rr >> 4, w = rr & 15;
    int a = A[((size_t)(bi * N_ + s)) * N_ + w * 32 + lane];
    unsigned int m0 = __ballot_sync(0xffffffffu, a == 4 || a == 2);
    unsigned int m1 = __ballot_sync(0xffffffffu, a == 4 || a == 3);
    if (lane == 0) g_mask[((size_t)(bi * 2 + 0) * N_ + s) * 16 + w] = m0;
    if (lane == 1) g_mask[((size_t)(bi * 2 + 1) * N_ + s) * 16 + w] = m1;
}

// ============================================================================
// Kernel 1: projection xp = x @ W^T + pb via 3xTF32 mma (fp32-accurate).
// grid (8 row-tiles of 64, 64 bic), 256 thr (8 warps = 2m x 4n, 32x32 tiles).
// K=128 in 4 chunks of 32, cp.async double-buffered.
// smem/stage: x[64][36] + W[128][36].
// ============================================================================
#define PJ_X_F (64 * 36)
#define PJ_STAGE_F (PJ_X_F + 128 * 36)     // 6912 floats
#define PJ_SMEM_BYTES (2 * PJ_STAGE_F * 4) // 55296

__global__ __launch_bounds__(256, 2) void proj_kernel(
    const float* __restrict__ x, const float* __restrict__ W, const float* __restrict__ pb)
{
    extern __shared__ __align__(16) float smem[];
    const int bic = blockIdx.y;
    const int mt  = blockIdx.x;
    const int c    = bic & 1;
    const int bi   = bic >> 1;
    const int iord = bi & 1;
    const int tid  = threadIdx.x;
    const int lane = tid & 31, warp = tid >> 5;
    const int wm = warp & 1, wn = warp >> 1;
    const int g  = lane >> 2, tg = lane & 3;

    const unsigned int sbase = smem_u32(smem);
    const float* xb = x + ((size_t)bi * N_ + mt * 64) * D_;
    const float* Wb = W + (size_t)(iord * 2 + c) * D_ * D_;

    auto issue = [&](int kc, int buf) {
        const unsigned int bb = sbase + (unsigned)(buf * PJ_STAGE_F * 4);
#pragma unroll
        for (int j = 0; j < 2; j++) {          // x: 64 rows
            int idx = tid + j * 256;
            int r = idx >> 3, kq = idx & 7;
            cpa16(bb + (unsigned)((r * 36 + kq * 4) * 4),
                  xb + (size_t)r * D_ + kc * 32 + kq * 4);
        }
#pragma unroll
        for (int j = 0; j < 4; j++) {          // W: 128 rows
            int idx = tid + j * 256;
            int r = idx >> 3, kq = idx & 7;
            cpa16(bb + (unsigned)((PJ_X_F + r * 36 + kq * 4) * 4),
                  Wb + (size_t)r * D_ + kc * 32 + kq * 4);
        }
        cpa_commit();
    };

    float c_[2][4][4];
#pragma unroll
    for (int f = 0; f < 2; f++)
#pragma unroll
        for (int n = 0; n < 4; n++)
#pragma unroll
            for (int k = 0; k < 4; k++) c_[f][n][k] = 0.0f;

    issue(0, 0);

#pragma unroll 1
    for (int kc = 0; kc < 4; kc++) {
        cpa_wait0();
        __syncthreads();
        if (kc < 3) issue(kc + 1, (kc + 1) & 1);
        const float* xs = smem + (kc & 1) * PJ_STAGE_F;
        const float* ws = xs + PJ_X_F;

#pragma unroll
        for (int k8 = 0; k8 < 4; k8++) {
            const int k = k8 * 8;
            unsigned int ah[2][4], al[2][4];
#pragma unroll
            for (int f = 0; f < 2; f++) {
                const int r0 = wm * 32 + f * 16 + g;
                tf32_split(xs[(r0)     * 36 + k + tg],     ah[f][0], al[f][0]);
                tf32_split(xs[(r0 + 8) * 36 + k + tg],     ah[f][1], al[f][1]);
                tf32_split(xs[(r0)     * 36 + k + tg + 4], ah[f][2], al[f][2]);
                tf32_split(xs[(r0 + 8) * 36 + k + tg + 4], ah[f][3], al[f][3]);
            }
#pragma unroll
            for (int n = 0; n < 4; n++) {
                const int dr = wn * 32 + n * 8 + g;
                unsigned int bh0, bl0, bh1, bl1;
                tf32_split(ws[dr * 36 + k + tg],     bh0, bl0);
                tf32_split(ws[dr * 36 + k + tg + 4], bh1, bl1);
#pragma unroll
                for (int f = 0; f < 2; f++) {
                    mma_tf32(c_[f][n], ah[f][0], ah[f][1], ah[f][2], ah[f][3], bh0, bh1);
                    mma_tf32(c_[f][n], ah[f][0], ah[f][1], ah[f][2], ah[f][3], bl0, bl1);
                    mma_tf32(c_[f][n], al[f][0], al[f][1], al[f][2], al[f][3], bh0, bh1);
                }
            }
        }
    }

    // epilogue: + pb, store xp
    const float* pbp = pb + (iord * 2 + c) * D_;
#pragma unroll
    for (int n = 0; n < 4; n++) {
        const int dout = wn * 32 + n * 8 + 2 * tg;
        float2 pbv = *(const float2*)(pbp + dout);
#pragma unroll
        for (int f = 0; f < 2; f++) {
            const int r0 = mt * 64 + wm * 32 + f * 16 + g;
            float2 o0, o1;
            o0.x = c_[f][n][0] + pbv.x; o0.y = c_[f][n][1] + pbv.y;
            o1.x = c_[f][n][2] + pbv.x; o1.y = c_[f][n][3] + pbv.y;
            *(float2*)(g_xp + ((size_t)bic * N_ + r0)     * D_ + dout) = o0;
            *(float2*)(g_xp + ((size_t)bic * N_ + r0 + 8) * D_ + dout) = o1;
        }
    }
}

// ============================================================================
// Kernel 1b: per-(node,head) scores + exp forms from g_xp.
// ============================================================================
__global__ __launch_bounds__(256) void score_kernel(
    const float* __restrict__ asrc, const float* __restrict__ adst)
{
    int gid = blockIdx.x * 256 + threadIdx.x;   // 64*512*8
    int h = gid & 7;
    int n = (gid >> 3) & 511;
    int bic = gid >> 12;
    int c = bic & 1, iord = (bic >> 1) & 1;
    const float* xph = g_xp + ((size_t)bic * N_ + n) * D_ + h * DH_;
    const float* av = asrc + ((iord * 2 + c) * H_ + h) * DH_;
    const float* dv = adst + ((iord * 2 + c) * H_ + h) * DH_;
    float ps = 0.0f, pd = 0.0f;
#pragma unroll
    for (int j = 0; j < 4; j++) {
        float4 xv = *(const float4*)(xph + j * 4);
        float4 a4 = *(const float4*)(av + j * 4);
        float4 d4 = *(const float4*)(dv + j * 4);
        ps += xv.x * a4.x + xv.y * a4.y + xv.z * a4.z + xv.w * a4.w;
        pd += xv.x * d4.x + xv.y * d4.y + xv.z * d4.z + xv.w * d4.w;
    }
    size_t o = ((size_t)bic * N_ + n) * H_ + h;
    *(float2*)(g_src2 + o * 2) = make_float2(__expf(ps), __expf(0.2f * ps));
    *(float2*)(g_dst2 + o * 2) = make_float2(__expf(pd), __expf(0.2f * pd));
}

// ============================================================================
// Kernel 2: attention via mma tf32; 64-dst tiles; truncation instead of cvt;
//           pre-shifted mask words with immediate bit tests.
// grid (8 dtiles x 64 bic), 256 thr, warp = head; 4 m-tiles x 2 n-frags, K=512.
// ============================================================================
#define TS 32
#define SD_F 1152
#define BUF_F 4992
#define ATT_SMEM_BYTES ((SD_F + 2 * BUF_F) * 4)

__global__ __launch_bounds__(256, 2) void att_kernel(const float* __restrict__ bias)
{
    extern __shared__ __align__(16) float smem[];
    const int bic  = blockIdx.y;
    const int tile = blockIdx.x;
    const int c    = bic & 1;
    const int bi   = bic >> 1;
    const int iord = bi & 1;
    const int tid  = threadIdx.x;
    const int lane = tid & 31;
    const int h    = tid >> 5;           // warp = head
    const int row  = lane >> 2;          // mma group id
    const int qid  = lane & 3;

    const unsigned int sbase = smem_u32(smem);
    const float* xp    = g_xp   + (size_t)bic * N_ * D_;
    const float* src2p = g_src2 + (size_t)bic * N_ * H_ * 2;
    const float* dst2p = g_dst2 + (size_t)bic * N_ * H_ * 2;
    const unsigned int* mgp = g_mask + (size_t)bic * N_ * 16 + tile * 2;

    const int xs_s = tid >> 5, xs_fq = tid & 31;
    const int ss_s = tid >> 3, ss_h = tid & 7;

    auto issue = [&](int t, int buf) {
        const int s0 = t * TS;
        const unsigned int b = sbase + (SD_F + buf * BUF_F) * 4;
#pragma unroll
        for (int k = 0; k < 4; k++) {
            int s = xs_s + k * 8;
            cpa16(b + (unsigned)(s * 544 + xs_fq * 16),
                  xp + (size_t)(s0 + s) * D_ + xs_fq * 4);
        }
        cpa8(b + 17408u + (unsigned)((ss_s * 9 + ss_h) * 8),
             src2p + ((size_t)(s0 + ss_s) * H_ + ss_h) * 2);
        if (tid < 32)
            cpa8(b + 19712u + (unsigned)(tid * 8), mgp + (size_t)(s0 + tid) * 16);
        cpa_commit();
    };

    // preload sd (64 dst x 8 h float2) + first tile
#pragma unroll
    for (int k = 0; k < 2; k++) {
        int idx = tid + k * 256;
        int d = idx >> 3, hh = idx & 7;
        cpa8(sbase + (unsigned)((d * 9 + hh) * 8),
             dst2p + ((size_t)(tile * 64 + d) * H_ + hh) * 2);
    }
    issue(0, 0);
    cpa_wait0();
    __syncthreads();

    // hoist destination-side exp pairs into registers
    float2 qA[4], qB[4];
#pragma unroll
    for (int m = 0; m < 4; m++) {
        qA[m] = *(const float2*)(smem + ((m * 16 + row) * 9 + h) * 2);
        qB[m] = *(const float2*)(smem + ((m * 16 + row + 8) * 9 + h) * 2);
    }

    float c_[4][2][4];
    float z_[4][2];
#pragma unroll
    for (int m = 0; m < 4; m++) {
        z_[m][0] = 0.0f; z_[m][1] = 0.0f;
#pragma unroll
        for (int j = 0; j < 2; j++)
#pragma unroll
            for (int k = 0; k < 4; k++) c_[m][j][k] = 0.0f;
    }

    issue(1, 1);

#pragma unroll 1
    for (int t = 0; t < N_ / TS; t++) {
        const int p = t & 1;
        if (t > 0) {
            cpa_wait0();
            __syncthreads();
            if (t < N_ / TS - 1) issue(t + 1, 1 - p);
        }

        const float* xhp = smem + SD_F + p * BUF_F;
        const float* ssp = xhp + 4352;
        const unsigned int* mkp = (const unsigned int*)(ssp + 576);

#pragma unroll
        for (int kc = 0; kc < 4; kc++) {
            const int s_lo = kc * 8 + qid;
            const int s_hi = s_lo + 4;
            float2 pA = *(const float2*)(ssp + (s_lo * 9 + h) * 2);
            float2 pB = *(const float2*)(ssp + (s_hi * 9 + h) * 2);
            uint2 mA2 = *(const uint2*)(mkp + s_lo * 2);
            uint2 mB2 = *(const uint2*)(mkp + s_hi * 2);
            // pre-shift mask words by this thread's row (bits at 0/8/16/24)
            const unsigned int uA0 = mA2.x >> row, uA1 = mA2.y >> row;
            const unsigned int uB0 = mB2.x >> row, uB1 = mB2.y >> row;
            unsigned int b0[2], b1[2];
#pragma unroll
            for (int j = 0; j < 2; j++) {
                int f = h * 16 + j * 8 + row;
                b0[j] = __float_as_uint(xhp[s_lo * 136 + f]) & TF32_TRUNC;
                b1[j] = __float_as_uint(xhp[s_hi * 136 + f]) & TF32_TRUNC;
            }
#pragma unroll
            for (int m = 0; m < 4; m++) {
                const unsigned int wA = (m < 2) ? uA0 : uA1;
                const unsigned int wB = (m < 2) ? uB0 : uB1;
                const unsigned int bitLo = 1u   << ((m & 1) << 4);
                const unsigned int bitHi = 256u << ((m & 1) << 4);
                float e00 = fmaxf(pA.x * qA[m].x, pA.y * qA[m].y);
                float e10 = fmaxf(pA.x * qB[m].x, pA.y * qB[m].y);
                float e01 = fmaxf(pB.x * qA[m].x, pB.y * qA[m].y);
                float e11 = fmaxf(pB.x * qB[m].x, pB.y * qB[m].y);
                unsigned int a0 = (wA & bitLo) ? (__float_as_uint(e00) & TF32_TRUNC) : ONE_BITS;
                unsigned int a1 = (wA & bitHi) ? (__float_as_uint(e10) & TF32_TRUNC) : ONE_BITS;
                unsigned int a2 = (wB & bitLo) ? (__float_as_uint(e01) & TF32_TRUNC) : ONE_BITS;
                unsigned int a3 = (wB & bitHi) ? (__float_as_uint(e11) & TF32_TRUNC) : ONE_BITS;
                // Z uses the SAME truncated weights as the numerator mma
                z_[m][0] += __uint_as_float(a0) + __uint_as_float(a2);
                z_[m][1] += __uint_as_float(a1) + __uint_as_float(a3);
                mma_tf32(c_[m][0], a0, a1, a2, a3, b0[0], b1[0]);
                mma_tf32(c_[m][1], a0, a1, a2, a3, b0[1], b1[1]);
            }
        }
    }

    // epilogue: reduce Z over quad, /Z, +xp, +bias, store
    const float* biasp = bias + (iord * 2 + c) * D_;
#pragma unroll
    for (int m = 0; m < 4; m++) {
        float z0 = z_[m][0];
        z0 += __shfl_xor_sync(0xffffffffu, z0, 1);
        z0 += __shfl_xor_sync(0xffffffffu, z0, 2);
        float z1 = z_[m][1];
        z1 += __shfl_xor_sync(0xffffffffu, z1, 1);
        z1 += __shfl_xor_sync(0xffffffffu, z1, 2);
        const float i0 = 1.0f / z0, i1 = 1.0f / z1;
        const int dA = tile * 64 + m * 16 + row;
        const int dB = dA + 8;
#pragma unroll
        for (int j = 0; j < 2; j++) {
            const int f = h * 16 + j * 8 + 2 * qid;
            float2 xA = *(const float2*)(xp + (size_t)dA * D_ + f);
            float2 xB = *(const float2*)(xp + (size_t)dB * D_ + f);
            float2 bb = *(const float2*)(biasp + f);
            float2 oA, oB;
            oA.x = c_[m][j][0] * i0 + xA.x + bb.x;
            oA.y = c_[m][j][1] * i0 + xA.y + bb.y;
            oB.x = c_[m][j][2] * i1 + xB.x + bb.x;
            oB.y = c_[m][j][3] * i1 + xB.y + bb.y;
            *(float2*)(g_att + ((size_t)bic * N_ + dA) * D_ + f) = oA;
            *(float2*)(g_att + ((size_t)bic * N_ + dB) * D_ + f) = oB;
        }
    }
}

// ============================================================================
// Kernel 3: combine.
// ============================================================================
__global__ void combine_kernel(float4* __restrict__ out) {
    int gid = blockIdx.x * blockDim.x + threadIdx.x;
    int b = gid >> 14;
    int r = gid & 16383;
    const float4* a = (const float4*)g_att;
    float4 a00 = a[(size_t)(b * 4 + 0) * 16384 + r];
    float4 a01 = a[(size_t)(b * 4 + 1) * 16384 + r];
    float4 a10 = a[(size_t)(b * 4 + 2) * 16384 + r];
    float4 a11 = a[(size_t)(b * 4 + 3) * 16384 + r];
    float4 h0, h1, o0, o1;
    h0.x = a00.x + a01.x; h0.y = a00.y + a01.y; h0.z = a00.z + a01.z; h0.w = a00.w + a01.w;
    h1.x = a10.x + a11.x; h1.y = a10.y + a11.y; h1.z = a10.z + a11.z; h1.w = a10.w + a11.w;
    float mx = 0.5f * (h0.x + h1.x), my = 0.5f * (h0.y + h1.y);
    float mz = 0.5f * (h0.z + h1.z), mw = 0.5f * (h0.w + h1.w);
    o0.x = h0.x + mx; o0.y = h0.y + my; o0.z = h0.z + mz; o0.w = h0.w + mw;
    o1.x = h1.x + mx; o1.y = h1.y + my; o1.z = h1.z + mz; o1.w = h1.w + mw;
    out[(size_t)(b * 2 + 0) * 16384 + r] = o0;
    out[(size_t)(b * 2 + 1) * 16384 + r] = o1;
}

// ============================================================================
extern "C" void kernel_launch(void* const* d_in, const int* in_sizes, int n_in,
                              void* d_out, int out_size) {
    const float* x    = (const float*)d_in[0];
    const int*   A    = (const int*)  d_in[1];
    const float* W    = (const float*)d_in[2];
    const float* pb   = (const float*)d_in[3];
    const float* asrc = (const float*)d_in[4];
    const float* adst = (const float*)d_in[5];
    const float* bias = (const float*)d_in[6];

    cudaFuncSetAttribute(proj_kernel, cudaFuncAttributeMaxDynamicSharedMemorySize,
                         PJ_SMEM_BYTES);
    cudaFuncSetAttribute(att_kernel, cudaFuncAttributeMaxDynamicSharedMemorySize,
                         ATT_SMEM_BYTES);

    mask_kernel<<<32768, 256>>>(A);
    proj_kernel<<<dim3(8, 64), 256, PJ_SMEM_BYTES>>>(x, W, pb);
    score_kernel<<<1024, 256>>>(asrc, adst);
    att_kernel<<<dim3(8, 64), 256, ATT_SMEM_BYTES>>>(bias);
    combine_kernel<<<1024, 256>>>((float4*)d_out);
}